// round 15
// baseline (speedup 1.0000x reference)
#include <cuda_runtime.h>
#include <math.h>

#define LD 65  // padded row stride for 64x64 tiles in smem

// ---------------- intermediates (device globals; no allocation allowed) -----------
__device__ float g_u1[64 * 512];
__device__ float g_u2[64 * 512];
__device__ float g_e1[64 * 512];
__device__ float g_e2[64 * 512];
__device__ float g_P[64 * 64];   // P[a,b] = e1n[b] . e2n[a]
__device__ unsigned g_c1 = 0, g_c2 = 0, g_cx = 0;   // grid-sync counters

__device__ __forceinline__ float warpSum(float v) {
#pragma unroll
    for (int o = 16; o; o >>= 1) v += __shfl_xor_sync(0xffffffffu, v, o);
    return v;
}
__device__ __forceinline__ float warpMax(float v) {
#pragma unroll
    for (int o = 16; o; o >>= 1) v = fmaxf(v, __shfl_xor_sync(0xffffffffu, v, o));
    return v;
}
__device__ __forceinline__ float dual16(float v) {
#pragma unroll
    for (int o = 8; o; o >>= 1) v += __shfl_xor_sync(0xffffffffu, v, o);
    return v;
}

// grid-wide sync across 128 co-resident blocks (arrive + spin; counter reset at exit)
__device__ __forceinline__ void gsync(unsigned* cnt) {
    __syncthreads();
    if (threadIdx.x == 0) {
        __threadfence();
        atomicAdd(cnt, 1u);
        while (atomicAdd(cnt, 0u) < 128u) {}
        __threadfence();
    }
    __syncthreads();
}

// ---------------- persistent front: Mp0+m+u -> sync -> eGEMM -> sync -> P ----------
// 128 blocks x 512 threads. All FP per-output accumulation orders identical to the
// R14 separate kernels (bit-identical results; only launch structure changed).
__global__ void __launch_bounds__(512) k_front(const float* __restrict__ tra,
                                               const float* __restrict__ det,
                                               const float* __restrict__ iou,
                                               const float* __restrict__ W,
                                               const float* __restrict__ bias) {
    __shared__ float As[64][16];   // [k][m] (Phase B/C staging)
    __shared__ float Bs[64][32];   // [k][j]
    __shared__ float mp[64];
    __shared__ float pf[16], pm[16];
    __shared__ float sLam;

    int t = threadIdx.x, w = t >> 5, lane = t & 31;

    // ================= Phase A: fused Mp0 + m + u (identical to k_front1) ==========
    {
        int rr = blockIdx.x;
        bool rowm = rr < 64;
        int r2 = rowm ? rr : rr - 64;
        const float* f = (rowm ? tra : det) + r2 * 512;
        const float* B = rowm ? det : tra;
        float* u = (rowm ? g_u1 : g_u2) + r2 * 512;

        int j0 = w * 4;
        float s0 = 0.f, s1 = 0.f, s2 = 0.f, s3 = 0.f;
        const float* b0p = B + (j0 + 0) * 512;
        const float* b1p = B + (j0 + 1) * 512;
        const float* b2p = B + (j0 + 2) * 512;
        const float* b3p = B + (j0 + 3) * 512;
#pragma unroll 4
        for (int k = lane; k < 512; k += 32) {
            float a = f[k];
            s0 += a * b0p[k]; s1 += a * b1p[k]; s2 += a * b2p[k]; s3 += a * b3p[k];
        }
        s0 = warpSum(s0); s1 = warpSum(s1); s2 = warpSum(s2); s3 = warpSum(s3);
        if (!lane) {
            if (rowm) {
                mp[j0 + 0] = s0 + iou[r2 * 64 + j0 + 0];
                mp[j0 + 1] = s1 + iou[r2 * 64 + j0 + 1];
                mp[j0 + 2] = s2 + iou[r2 * 64 + j0 + 2];
                mp[j0 + 3] = s3 + iou[r2 * 64 + j0 + 3];
            } else {
                mp[j0 + 0] = s0 + iou[(j0 + 0) * 64 + r2];
                mp[j0 + 1] = s1 + iou[(j0 + 1) * 64 + r2];
                mp[j0 + 2] = s2 + iou[(j0 + 2) * 64 + r2];
                mp[j0 + 3] = s3 + iou[(j0 + 3) * 64 + r2];
            }
        }
        __syncthreads();

        float mv = 0.f;
#pragma unroll 8
        for (int j = 0; j < 64; j++) mv += mp[j] * B[j * 512 + t];
        float fv = f[t];
        float sf = warpSum(fv * fv);
        float smv = warpSum(mv * mv);
        if (!lane) { pf[w] = sf; pm[w] = smv; }
        __syncthreads();
        if (t < 32) {
            float a = (t < 16) ? pf[t] : 0.f;
            float b = (t < 16) ? pm[t] : 0.f;
            a = warpSum(a);
            b = warpSum(b);
            if (!t) sLam = sqrtf(a) / sqrtf(b);
        }
        __syncthreads();
        u[t] = fv + sLam * mv;
    }

    gsync(&g_c1);   // all g_u written

    // ================= Phase B: e = relu(u @ W^T + b), tile 16m x 32j ==============
    // Block b: mt = b>>4 (0..7), jt = b&15. One output/thread; k accumulated
    // sequentially 0..511 -> bit-identical to the 2x2-micro version.
    {
        int mt = blockIdx.x >> 4;
        int jt = blockIdx.x & 15;
        const float* u = (mt < 4) ? g_u1 : g_u2;
        float* e = (mt < 4) ? g_e1 : g_e2;
        int m0 = (mt & 3) * 16;
        int j0 = jt * 32;
        int om = w >> 1;                       // not used; recompute below
        (void)om;
        int tm = t >> 5, tj = t & 31;          // output (m0+tm, j0+tj)
        float acc = 0.f;
        for (int c = 0; c < 8; c++) {
            int kc = c * 64;
            // stage As: 16 rows x 64 k = 256 float4; threads 0..255
            if (t < 256) {
                int row = t >> 4, q = t & 15;
                float4 v = *(const float4*)(u + (m0 + row) * 512 + kc + 4 * q);
                As[4 * q + 0][row] = v.x; As[4 * q + 1][row] = v.y;
                As[4 * q + 2][row] = v.z; As[4 * q + 3][row] = v.w;
            }
            // stage Bs: 32 rows x 64 k = 512 float4; all threads
            {
                int row = t >> 4, q = t & 15;
                float4 v = *(const float4*)(W + (j0 + row) * 512 + kc + 4 * q);
                Bs[4 * q + 0][row] = v.x; Bs[4 * q + 1][row] = v.y;
                Bs[4 * q + 2][row] = v.z; Bs[4 * q + 3][row] = v.w;
            }
            __syncthreads();
#pragma unroll 16
            for (int k = 0; k < 64; k++) acc += As[k][tm] * Bs[k][tj];
            __syncthreads();
        }
        e[(m0 + tm) * 512 + j0 + tj] = fmaxf(acc + bias[j0 + tj], 0.f);
    }

    gsync(&g_c2);   // all g_e written

    // ================= Phase C: P[a,b] = e2[a].e1[b]/(|e2[a]||e1[b]|) ==============
    // 8 tiles of 16a x 32b on blocks 0..7; one output/thread; k sequential.
    if (blockIdx.x < 8) {
        int a0 = (blockIdx.x >> 1) * 16;
        int b0 = (blockIdx.x & 1) * 32;
        int ta = t >> 5, tb = t & 31;
        float acc = 0.f, na = 0.f, nb = 0.f;
        for (int c = 0; c < 8; c++) {
            int kc = c * 64;
            if (t < 256) {
                int row = t >> 4, q = t & 15;
                float4 v = *(const float4*)(g_e2 + (a0 + row) * 512 + kc + 4 * q);
                As[4 * q + 0][row] = v.x; As[4 * q + 1][row] = v.y;
                As[4 * q + 2][row] = v.z; As[4 * q + 3][row] = v.w;
            }
            {
                int row = t >> 4, q = t & 15;
                float4 v = *(const float4*)(g_e1 + (b0 + row) * 512 + kc + 4 * q);
                Bs[4 * q + 0][row] = v.x; Bs[4 * q + 1][row] = v.y;
                Bs[4 * q + 2][row] = v.z; Bs[4 * q + 3][row] = v.w;
            }
            __syncthreads();
#pragma unroll 16
            for (int k = 0; k < 64; k++) {
                float av = As[k][ta], bv = Bs[k][tb];
                acc += av * bv;
                na += av * av;
                nb += bv * bv;
            }
            __syncthreads();
        }
        float denom = fmaxf(sqrtf(na), 1e-12f) * fmaxf(sqrtf(nb), 1e-12f);
        g_P[(a0 + ta) * 64 + b0 + tb] = acc / denom;
    }

    // ---- exit protocol: block 0 resets counters after ALL blocks arrive ----
    __syncthreads();
    if (threadIdx.x == 0) {
        __threadfence();
        atomicAdd(&g_cx, 1u);
        if (blockIdx.x == 0) {
            while (atomicAdd(&g_cx, 0u) < 128u) {}
            atomicExch(&g_c1, 0u);
            atomicExch(&g_c2, 0u);
            atomicExch(&g_cx, 0u);
        }
    }
}

// ---------------- ADMM + PCG, Woodbury precond + closed-form alpha -----------------
// Termination: (a) CG skip when N2<=tol2 for 6 outers, OR (b) x-stagnation:
// |x - x_prev|^2 <= 1e-9 |x|^2 for 2 consecutive outers. CG tol 1e-8 (R9-validated).
__global__ void __launch_bounds__(1024, 1) k_admm(float* __restrict__ out) {
    extern __shared__ float smx[];
    float* X    = smx;             // 4160 each
    float* Rr   = smx + 4160;
    float* Dd   = smx + 8320;
    float* Pm   = smx + 12480;
    float* RAd  = smx + 16640;     // 64 each
    float* CAd  = RAd + 64;
    float* RBd  = CAd + 64;
    float* CBd  = RBd + 64;
    float* RD2  = CBd + 64;
    float* RPD2 = RD2 + 64;
    float* RAr  = RPD2 + 64;
    float* CAr  = RAr + 64;
    float* RSQ  = CAr + 64;
    float* RPR  = RSQ + 64;
    float* RP   = RPR + 64;
    float* CP   = RP + 64;
    float* RX   = CP + 64;
    float* CX   = RX + 64;
    float* y2r  = CX + 64;
    float* y2c  = y2r + 64;
    float* part = y2c + 64;        // 32
    float* prt2 = part + 32;       // 32
    float* scal = prt2 + 32;       // 8

    const float rho   = 100.f;
    const float sigma = 1e-3f;
    const float beta  = 3969.f + rho + sigma;
    const float binv  = 1.f / beta;
    const float b64i  = 1.f / (beta + 64.f * rho);
    const float b128i = 1.f / (beta + 128.f * rho);
    const float cRC   = (b64i - binv) * (1.f / 64.f);
    const float cT    = (b128i - 2.f * b64i + binv) * (1.f / 4096.f);

    const int tid = threadIdx.x;
    const int w = tid >> 5, lane = tid & 31;
    const int g = lane & 15, h = lane >> 4;
    const int a0 = tid >> 6, b0 = tid & 63;
    const int rc = 2 * w + h;

    int aa[4], off[4];
#pragma unroll
    for (int k = 0; k < 4; k++) { aa[k] = a0 + 16 * k; off[k] = aa[k] * LD + b0; }

    float x[4], xr[4], z1[4], y1[4], r[4], p[4], dreg[4], wp[4];
#pragma unroll
    for (int k = 0; k < 4; k++) {
        p[k] = g_P[aa[k] * 64 + b0];
        Pm[off[k]] = p[k];
        X[off[k]] = 0.f;
        x[k] = xr[k] = z1[k] = y1[k] = 0.f;
    }
    if (tid < 64) { y2r[tid] = 0.f; y2c[tid] = 0.f; RX[tid] = 0.f; CX[tid] = 0.f; }
    __syncthreads();

    // ---- init: sums over P for Woodbury ----
    {
        float sv = 0.f, sq = 0.f;
#pragma unroll
        for (int j = 0; j < 4; j++) {
            float v = Pm[rc * LD + g + 16 * j];
            sv += v; sq += v * v;
        }
        sv = dual16(sv); sq = dual16(sq);
        if (!g) { RP[rc] = sv; RSQ[rc] = sq; }
        float cv = 0.f;
#pragma unroll
        for (int j = 0; j < 4; j++) cv += Pm[(g + 16 * j) * LD + rc];
        cv = dual16(cv);
        if (!g) CP[rc] = cv;
        __syncthreads();
        if (w == 0)      { float v = warpSum(RP[lane] + RP[lane + 32]);  if (!lane) scal[5] = v; }
        else if (w == 1) { float v = warpSum(RSQ[lane] + RSQ[lane + 32]); if (!lane) scal[6] = v; }
        else if (w == 2) { float v = warpSum(RP[lane] * RP[lane] + RP[lane + 32] * RP[lane + 32]
                                           + CP[lane] * CP[lane] + CP[lane + 32] * CP[lane + 32]);
                           if (!lane) scal[7] = v; }
        __syncthreads();
    }
    const float TP = scal[5];
    const float P2 = scal[6];
    const float SRCP2 = scal[7];
    const float pBp = binv * P2 + cRC * SRCP2 + cT * TP * TP;
    const float h12v = 2.f - b128i * TP;
    const float h11v = -pBp;
    const float h22v = -4096.f * b128i;
    const float hdet = h11v * h22v - h12v * h12v;
    const float i11 = h22v / hdet, i12 = -h12v / hdet, i22 = h11v / hdet;
#pragma unroll
    for (int k = 0; k < 4; k++)
        wp[k] = binv * p[k] + cRC * (RP[aa[k]] + CP[b0]) + cT * TP;

    float TA = 0.f, TB = 0.f, D2 = 0.f, PD2 = 0.f, SA2 = 0.f, SAB = 0.f;
    float TR = 0.f, N2 = 0.f, SRC2 = 0.f, SPC = 0.f, PR = 0.f;
    float tol2 = 1e30f;
    int conv = 0, convS = 0;

    auto phaseD = [&]() {
        float sv = 0.f, sp = 0.f, sq = 0.f, spq = 0.f;
#pragma unroll
        for (int j = 0; j < 4; j++) {
            int o = rc * LD + g + 16 * j;
            float m = Dd[o], q = Pm[o];
            sv += m; sp += q * m; sq += m * m; spq += q * m * m;
        }
        sv = dual16(sv); sp = dual16(sp); sq = dual16(sq); spq = dual16(spq);
        if (!g) { RAd[rc] = sv; RBd[rc] = sp; RD2[rc] = sq; RPD2[rc] = spq; }
        float cv = 0.f, cp = 0.f;
#pragma unroll
        for (int j = 0; j < 4; j++) {
            int o = (g + 16 * j) * LD + rc;
            float m = Dd[o];
            cv += m; cp += Pm[o] * m;
        }
        cv = dual16(cv); cp = dual16(cp);
        if (!g) { CAd[rc] = cv; CBd[rc] = cp; }
        __syncthreads();
        if (w == 0)      { float v = warpSum(RAd[lane] + RAd[lane + 32]);  if (!lane) scal[0] = v; }
        else if (w == 1) { float v = warpSum(RBd[lane] + RBd[lane + 32]);  if (!lane) scal[1] = v; }
        else if (w == 2) { float v = warpSum(RD2[lane] + RD2[lane + 32]);  if (!lane) scal[2] = v; }
        else if (w == 3) { float v = warpSum(RPD2[lane] + RPD2[lane + 32]); if (!lane) scal[3] = v; }
        else if (w == 4) { float v = warpSum(RAd[lane] * RAd[lane] + RAd[lane + 32] * RAd[lane + 32]
                                           + CAd[lane] * CAd[lane] + CAd[lane + 32] * CAd[lane + 32]);
                           if (!lane) scal[4] = v; }
        else if (w == 5) { float v = warpSum(RAd[lane] * RBd[lane] + RAd[lane + 32] * RBd[lane + 32]
                                           + CAd[lane] * CBd[lane] + CAd[lane + 32] * CBd[lane + 32]);
                           if (!lane) scal[5] = v; }
        __syncthreads();
        TA = scal[0]; TB = scal[1]; D2 = scal[2]; PD2 = scal[3]; SA2 = scal[4]; SAB = scal[5];
    };

    auto phaseR = [&]() {
        float sv = 0.f, sq = 0.f, pv = 0.f;
#pragma unroll
        for (int j = 0; j < 4; j++) {
            int o = rc * LD + g + 16 * j;
            float v = Rr[o];
            sv += v; sq += v * v; pv += Pm[o] * v;
        }
        sv = dual16(sv); sq = dual16(sq); pv = dual16(pv);
        if (!g) { RAr[rc] = sv; RSQ[rc] = sq; RPR[rc] = pv; }
        float cv = 0.f;
#pragma unroll
        for (int j = 0; j < 4; j++) cv += Rr[(g + 16 * j) * LD + rc];
        cv = dual16(cv);
        if (!g) CAr[rc] = cv;
        __syncthreads();
        if (w == 0)      { float v = warpSum(RAr[lane] + RAr[lane + 32]); if (!lane) scal[0] = v; }
        else if (w == 1) { float v = warpSum(RSQ[lane] + RSQ[lane + 32]); if (!lane) scal[1] = v; }
        else if (w == 2) { float v = warpSum(RAr[lane] * RAr[lane] + RAr[lane + 32] * RAr[lane + 32]
                                           + CAr[lane] * CAr[lane] + CAr[lane + 32] * CAr[lane + 32]);
                           if (!lane) scal[2] = v; }
        else if (w == 3) { float v = warpSum(RP[lane] * RAr[lane] + RP[lane + 32] * RAr[lane + 32]
                                           + CP[lane] * CAr[lane] + CP[lane + 32] * CAr[lane + 32]);
                           if (!lane) scal[3] = v; }
        else if (w == 4) { float v = warpSum(RPR[lane] + RPR[lane + 32]); if (!lane) scal[4] = v; }
        __syncthreads();
        TR = scal[0]; N2 = scal[1]; SRC2 = scal[2]; SPC = scal[3]; PR = scal[4];
    };

    auto applyK = [&](float d, float pp, int a) -> float {
        float Ra = RAd[a], Cb = CAd[b0], Rb = RBd[a], Cv = CBd[b0];
        return beta * d + rho * (Ra + Cb)
             - 0.5f * (pp * (TA - Ra - Cb + d) + (TB - Rb - Cv + pp * d));
    };

    float s1 = 0.f, s2 = 0.f, al1 = 0.f, al2 = 0.f, rhoz = 0.f;
    auto wood = [&]() {
        s1 = binv * PR + cRC * SPC + cT * TP * TR;
        s2 = b128i * TR;
        al1 = i11 * s1 + i12 * s2;
        al2 = i12 * s1 + i22 * s2;
        rhoz = binv * N2 + cRC * SRC2 + cT * TR * TR + al1 * s1 + al2 * s2;
    };

    for (int it = 0; it < 150; ++it) {
        if ((it & 7) == 0) {
            // refresh residual from scratch: publish X, strip sums, r = rhs - Kx
#pragma unroll
            for (int k = 0; k < 4; k++) X[off[k]] = x[k];
            __syncthreads();
            {
                float sv = 0.f, sp = 0.f;
#pragma unroll
                for (int j = 0; j < 4; j++) {
                    int o = rc * LD + g + 16 * j;
                    float m = X[o];
                    sv += m; sp += Pm[o] * m;
                }
                sv = dual16(sv); sp = dual16(sp);
                if (!g) { RAd[rc] = sv; RBd[rc] = sp; }
                float cv = 0.f, cp = 0.f;
#pragma unroll
                for (int j = 0; j < 4; j++) {
                    int o = (g + 16 * j) * LD + rc;
                    float m = X[o];
                    cv += m; cp += Pm[o] * m;
                }
                cv = dual16(cv); cp = dual16(cp);
                if (!g) { CAd[rc] = cv; CBd[rc] = cp; }
            }
            __syncthreads();
            TA = warpSum(RAd[lane] + RAd[lane + 32]);
            TB = warpSum(RBd[lane] + RBd[lane + 32]);
            float loc = 0.f;
#pragma unroll
            for (int k = 0; k < 4; k++) {
                float kx = applyK(x[k], p[k], aa[k]);
                float rhs = sigma * x[k] + p[k] + (rho * z1[k] - y1[k])
                          + (rho - y2c[b0]) + (rho - y2r[aa[k]]);
                r[k] = rhs - kx;
                Rr[off[k]] = r[k];
                loc += rhs * rhs;
            }
            loc = warpSum(loc);
            if (!lane) part[w] = loc;
            __syncthreads();
            float nr = warpSum(part[lane]);
            tol2 = fmaxf(nr * 1e-8f, 1e-28f);
            if (tid < 64) { RX[tid] = RAd[tid]; CX[tid] = CAd[tid]; }
            __syncthreads();
        }

        phaseR();

        if (N2 > tol2) {
            conv = 0;
            wood();
            float rho_s = rhoz;
#pragma unroll
            for (int k = 0; k < 4; k++) {
                float z = binv * r[k] + cRC * (RAr[aa[k]] + CAr[b0]) + cT * TR
                        + al1 * wp[k] + al2 * b128i;
                dreg[k] = z;
                Dd[off[k]] = z;
            }

            float prev = 3.4e38f;
            int stag = 0;
            for (int cg = 0; cg < 60; ++cg) {
                __syncthreads();
                phaseD();
                float dq = beta * D2 + rho * SA2 - (TA * TB - SAB + PD2);
                if (!(dq > 0.f)) break;
                float alpha = rho_s / dq;
#pragma unroll
                for (int k = 0; k < 4; k++) {
                    float q = applyK(dreg[k], p[k], aa[k]);
                    x[k] += alpha * dreg[k];
                    r[k] -= alpha * q;
                    Rr[off[k]] = r[k];
                }
                if (tid < 64) {
                    RX[tid] += alpha * RAd[tid];
                    CX[tid] += alpha * CAd[tid];
                }
                __syncthreads();
                phaseR();
                if (N2 <= tol2) break;
                if (N2 >= 0.99f * prev) { if (++stag >= 3) break; }
                else stag = 0;
                prev = N2;
                wood();
                float bk = rhoz / rho_s;
                rho_s = rhoz;
#pragma unroll
                for (int k = 0; k < 4; k++) {
                    float z = binv * r[k] + cRC * (RAr[aa[k]] + CAr[b0]) + cT * TR
                            + al1 * wp[k] + al2 * b128i;
                    dreg[k] = z + bk * dreg[k];
                    Dd[off[k]] = dreg[k];
                }
            }
        } else {
            if (++conv >= 6) break;       // ADMM fixed point: x frozen, stop
        }

        // z/y updates + incremental residual; also reduce |x-xr|^2 and |x|^2
        float locD = 0.f, locX = 0.f;
#pragma unroll
        for (int k = 0; k < 4; k++) {
            float z1n = fminf(fmaxf(x[k] + y1[k] * (1.f / rho), 0.f), 1e6f);
            float dx = x[k] - xr[k];
            float rinc = sigma * dx + rho * (2.f * z1n - z1[k] - x[k])
                       - rho * (CX[b0] - 1.f) - rho * (RX[aa[k]] - 1.f);
            y1[k] += rho * (x[k] - z1n);
            z1[k] = z1n;
            r[k] += rinc;
            Rr[off[k]] = r[k];
            xr[k] = x[k];
            locD += dx * dx;
            locX += x[k] * x[k];
        }
        locD = warpSum(locD);
        locX = warpSum(locX);
        if (!lane) { part[w] = locD; prt2[w] = locX; }
        if (tid < 64) {
            y2c[tid] += rho * (CX[tid] - 1.f);
            y2r[tid] += rho * (RX[tid] - 1.f);
        }
        __syncthreads();
        float delta2 = warpSum(part[lane]);
        float x2 = warpSum(prt2[lane]);
        if (delta2 <= 1e-9f * x2 + 1e-30f) {
            if (++convS >= 2) break;      // x stagnant 2 outers: converged
        } else convS = 0;
    }

    // publish final X, then column-wise softmax: out[0][j][i] = softmax_i(200*clip)
#pragma unroll
    for (int k = 0; k < 4; k++) X[off[k]] = x[k];
    __syncthreads();
#pragma unroll
    for (int rr = 0; rr < 2; rr++) {
        int c = 2 * w + rr;
        float v1 = fminf(fmaxf(X[lane * LD + c], 0.f), 1.f);
        float v2 = fminf(fmaxf(X[(lane + 32) * LD + c], 0.f), 1.f);
        float mx = warpMax(fmaxf(v1, v2));
        float e1v = expf(200.f * (v1 - mx));
        float e2v = expf(200.f * (v2 - mx));
        float s = warpSum(e1v + e2v);
        out[c * 64 + lane] = e1v / s;
        out[c * 64 + lane + 32] = e2v / s;
    }
}

// ------------------------------------------------------------------------------------
extern "C" void kernel_launch(void* const* d_in, const int* in_sizes, int n_in,
                              void* d_out, int out_size) {
    const float* tra = (const float*)d_in[0];   // (64,512)
    const float* det = (const float*)d_in[1];   // (64,512)
    const float* iou = (const float*)d_in[2];   // (64,64)
    const float* W   = (const float*)d_in[3];   // (512,512)
    const float* b   = (const float*)d_in[4];   // (512,)
    float* out = (float*)d_out;                 // (1,64,64)

    const int SMEM_BYTES = (16640 + 16 * 64 + 64 + 8) * 4;  // 70944
    cudaFuncSetAttribute(k_admm, cudaFuncAttributeMaxDynamicSharedMemorySize, SMEM_BYTES);

    k_front<<<128, 512>>>(tra, det, iou, W, b);
    k_admm<<<1, 1024, SMEM_BYTES>>>(out);
}

// round 17
// speedup vs baseline: 1.3406x; 1.3406x over previous
#include <cuda_runtime.h>
#include <math.h>

#define LD 65  // padded row stride for 64x64 tiles in smem

// ---------------- intermediates (device globals; no allocation allowed) -----------
__device__ float g_u1[64 * 512];
__device__ float g_u2[64 * 512];
__device__ float g_e1[64 * 512];
__device__ float g_e2[64 * 512];
__device__ float g_P[64 * 64];   // P[a,b] = e1n[b] . e2n[a]

__device__ __forceinline__ float warpSum(float v) {
#pragma unroll
    for (int o = 16; o; o >>= 1) v += __shfl_xor_sync(0xffffffffu, v, o);
    return v;
}
__device__ __forceinline__ float warpMax(float v) {
#pragma unroll
    for (int o = 16; o; o >>= 1) v = fmaxf(v, __shfl_xor_sync(0xffffffffu, v, o));
    return v;
}
__device__ __forceinline__ float dual16(float v) {
#pragma unroll
    for (int o = 8; o; o >>= 1) v += __shfl_xor_sync(0xffffffffu, v, o);
    return v;
}

// ---------------- fused Mp0 + m + u : one block per output row ---------------------
__global__ void __launch_bounds__(512) k_front1(const float* __restrict__ tra,
                                                const float* __restrict__ det,
                                                const float* __restrict__ iou) {
    __shared__ float mp[64];
    __shared__ float pf[16], pm[16];
    __shared__ float sLam;
    int rr = blockIdx.x;
    int t = threadIdx.x, w = t >> 5, lane = t & 31;
    bool rowm = rr < 64;
    int r2 = rowm ? rr : rr - 64;
    const float* f = (rowm ? tra : det) + r2 * 512;
    const float* B = rowm ? det : tra;
    float* u = (rowm ? g_u1 : g_u2) + r2 * 512;

    int j0 = w * 4;
    float s0 = 0.f, s1 = 0.f, s2 = 0.f, s3 = 0.f;
    const float* b0p = B + (j0 + 0) * 512;
    const float* b1p = B + (j0 + 1) * 512;
    const float* b2p = B + (j0 + 2) * 512;
    const float* b3p = B + (j0 + 3) * 512;
#pragma unroll 4
    for (int k = lane; k < 512; k += 32) {
        float a = f[k];
        s0 += a * b0p[k]; s1 += a * b1p[k]; s2 += a * b2p[k]; s3 += a * b3p[k];
    }
    s0 = warpSum(s0); s1 = warpSum(s1); s2 = warpSum(s2); s3 = warpSum(s3);
    if (!lane) {
        if (rowm) {
            mp[j0 + 0] = s0 + iou[r2 * 64 + j0 + 0];
            mp[j0 + 1] = s1 + iou[r2 * 64 + j0 + 1];
            mp[j0 + 2] = s2 + iou[r2 * 64 + j0 + 2];
            mp[j0 + 3] = s3 + iou[r2 * 64 + j0 + 3];
        } else {
            mp[j0 + 0] = s0 + iou[(j0 + 0) * 64 + r2];
            mp[j0 + 1] = s1 + iou[(j0 + 1) * 64 + r2];
            mp[j0 + 2] = s2 + iou[(j0 + 2) * 64 + r2];
            mp[j0 + 3] = s3 + iou[(j0 + 3) * 64 + r2];
        }
    }
    __syncthreads();

    float mv = 0.f;
#pragma unroll 8
    for (int j = 0; j < 64; j++) mv += mp[j] * B[j * 512 + t];
    float fv = f[t];
    float sf = warpSum(fv * fv);
    float smv = warpSum(mv * mv);
    if (!lane) { pf[w] = sf; pm[w] = smv; }
    __syncthreads();
    if (t < 32) {
        float a = (t < 16) ? pf[t] : 0.f;
        float b = (t < 16) ? pm[t] : 0.f;
        a = warpSum(a);
        b = warpSum(b);
        if (!t) sLam = sqrtf(a) / sqrtf(b);
    }
    __syncthreads();
    u[t] = fv + sLam * mv;
}

// ---------------- e = relu(u @ W^T + b) : 128-block tiled GEMM ---------------------
__global__ void __launch_bounds__(128) k_egemm(const float* __restrict__ W,
                                               const float* __restrict__ bias) {
    __shared__ float As[64][16];   // [k][m]
    __shared__ float Bs[64][32];   // [k][j]
    int tid = threadIdx.x;
    int mt = blockIdx.x >> 4;
    int jt = blockIdx.x & 15;
    const float* u = (mt < 4) ? g_u1 : g_u2;
    float* e = (mt < 4) ? g_e1 : g_e2;
    int m0 = (mt & 3) * 16;
    int j0 = jt * 32;
    int tr = tid >> 4, tc = tid & 15;
    float a00 = 0.f, a01 = 0.f, a10 = 0.f, a11 = 0.f;
    for (int c = 0; c < 8; c++) {
        int kc = c * 64;
#pragma unroll
        for (int s = 0; s < 2; s++) {
            int fI = tid * 2 + s, row = fI >> 4, q = fI & 15;
            float4 v = *(const float4*)(u + (m0 + row) * 512 + kc + 4 * q);
            As[4 * q + 0][row] = v.x; As[4 * q + 1][row] = v.y;
            As[4 * q + 2][row] = v.z; As[4 * q + 3][row] = v.w;
        }
#pragma unroll
        for (int s = 0; s < 4; s++) {
            int fI = tid * 4 + s, row = fI >> 4, q = fI & 15;
            float4 v = *(const float4*)(W + (j0 + row) * 512 + kc + 4 * q);
            Bs[4 * q + 0][row] = v.x; Bs[4 * q + 1][row] = v.y;
            Bs[4 * q + 2][row] = v.z; Bs[4 * q + 3][row] = v.w;
        }
        __syncthreads();
#pragma unroll 8
        for (int k = 0; k < 64; k++) {
            float2 a = *(const float2*)&As[k][2 * tr];
            float2 b = *(const float2*)&Bs[k][2 * tc];
            a00 += a.x * b.x; a01 += a.x * b.y;
            a10 += a.y * b.x; a11 += a.y * b.y;
        }
        __syncthreads();
    }
    float2 bv = *(const float2*)(bias + j0 + 2 * tc);
    {
        int m = m0 + 2 * tr;
        float2 o;
        o.x = fmaxf(a00 + bv.x, 0.f); o.y = fmaxf(a01 + bv.y, 0.f);
        *(float2*)(e + m * 512 + j0 + 2 * tc) = o;
        o.x = fmaxf(a10 + bv.x, 0.f); o.y = fmaxf(a11 + bv.y, 0.f);
        *(float2*)(e + (m + 1) * 512 + j0 + 2 * tc) = o;
    }
}

// ---------------- P[a,b] = e2[a].e1[b] / (|e2[a]||e1[b]|) : norms fused ------------
__global__ void __launch_bounds__(256) k_P() {
    __shared__ float As[64][16];
    __shared__ float Bs[64][16];
    int tid = threadIdx.x;
    int a0 = (blockIdx.x >> 2) * 16, b0 = (blockIdx.x & 3) * 16;
    int tr = tid >> 4, tc = tid & 15;
    int lrow = tid >> 4, lq = tid & 15;
    float acc = 0.f, na = 0.f, nb = 0.f;
    for (int c = 0; c < 8; c++) {
        int kc = c * 64;
        float4 va = *(const float4*)(g_e2 + (a0 + lrow) * 512 + kc + 4 * lq);
        As[4 * lq + 0][lrow] = va.x; As[4 * lq + 1][lrow] = va.y;
        As[4 * lq + 2][lrow] = va.z; As[4 * lq + 3][lrow] = va.w;
        float4 vb = *(const float4*)(g_e1 + (b0 + lrow) * 512 + kc + 4 * lq);
        Bs[4 * lq + 0][lrow] = vb.x; Bs[4 * lq + 1][lrow] = vb.y;
        Bs[4 * lq + 2][lrow] = vb.z; Bs[4 * lq + 3][lrow] = vb.w;
        __syncthreads();
#pragma unroll 16
        for (int k = 0; k < 64; k++) {
            float av = As[k][tr], bv = Bs[k][tc];
            acc += av * bv;
            na += av * av;
            nb += bv * bv;
        }
        __syncthreads();
    }
    float denom = fmaxf(sqrtf(na), 1e-12f) * fmaxf(sqrtf(nb), 1e-12f);
    g_P[(a0 + tr) * 64 + b0 + tc] = acc / denom;
}

// ---------------- ADMM + PCG, Woodbury precond + closed-form alpha -----------------
// Termination: (a) CG skip when N2<=tol2 for 6 outers, OR (b) x-stagnation:
// |x - x_prev|^2 <= 4e-9 |x|^2 for 2 consecutive outers. CG tol 1e-7.
__global__ void __launch_bounds__(1024, 1) k_admm(float* __restrict__ out) {
    extern __shared__ float smx[];
    float* X    = smx;             // 4160 each
    float* Rr   = smx + 4160;
    float* Dd   = smx + 8320;
    float* Pm   = smx + 12480;
    float* RAd  = smx + 16640;     // 64 each
    float* CAd  = RAd + 64;
    float* RBd  = CAd + 64;
    float* CBd  = RBd + 64;
    float* RD2  = CBd + 64;
    float* RPD2 = RD2 + 64;
    float* RAr  = RPD2 + 64;
    float* CAr  = RAr + 64;
    float* RSQ  = CAr + 64;
    float* RPR  = RSQ + 64;
    float* RP   = RPR + 64;
    float* CP   = RP + 64;
    float* RX   = CP + 64;
    float* CX   = RX + 64;
    float* y2r  = CX + 64;
    float* y2c  = y2r + 64;
    float* part = y2c + 64;        // 32
    float* prt2 = part + 32;       // 32
    float* scal = prt2 + 32;       // 8

    const float rho   = 100.f;
    const float sigma = 1e-3f;
    const float beta  = 3969.f + rho + sigma;
    const float binv  = 1.f / beta;
    const float b64i  = 1.f / (beta + 64.f * rho);
    const float b128i = 1.f / (beta + 128.f * rho);
    const float cRC   = (b64i - binv) * (1.f / 64.f);
    const float cT    = (b128i - 2.f * b64i + binv) * (1.f / 4096.f);

    const int tid = threadIdx.x;
    const int w = tid >> 5, lane = tid & 31;
    const int g = lane & 15, h = lane >> 4;
    const int a0 = tid >> 6, b0 = tid & 63;
    const int rc = 2 * w + h;

    int aa[4], off[4];
#pragma unroll
    for (int k = 0; k < 4; k++) { aa[k] = a0 + 16 * k; off[k] = aa[k] * LD + b0; }

    float x[4], xr[4], z1[4], y1[4], r[4], p[4], dreg[4], wp[4];
#pragma unroll
    for (int k = 0; k < 4; k++) {
        p[k] = g_P[aa[k] * 64 + b0];
        Pm[off[k]] = p[k];
        X[off[k]] = 0.f;
        x[k] = xr[k] = z1[k] = y1[k] = 0.f;
    }
    if (tid < 64) { y2r[tid] = 0.f; y2c[tid] = 0.f; RX[tid] = 0.f; CX[tid] = 0.f; }
    __syncthreads();

    // ---- init: sums over P for Woodbury ----
    {
        float sv = 0.f, sq = 0.f;
#pragma unroll
        for (int j = 0; j < 4; j++) {
            float v = Pm[rc * LD + g + 16 * j];
            sv += v; sq += v * v;
        }
        sv = dual16(sv); sq = dual16(sq);
        if (!g) { RP[rc] = sv; RSQ[rc] = sq; }
        float cv = 0.f;
#pragma unroll
        for (int j = 0; j < 4; j++) cv += Pm[(g + 16 * j) * LD + rc];
        cv = dual16(cv);
        if (!g) CP[rc] = cv;
        __syncthreads();
        if (w == 0)      { float v = warpSum(RP[lane] + RP[lane + 32]);  if (!lane) scal[5] = v; }
        else if (w == 1) { float v = warpSum(RSQ[lane] + RSQ[lane + 32]); if (!lane) scal[6] = v; }
        else if (w == 2) { float v = warpSum(RP[lane] * RP[lane] + RP[lane + 32] * RP[lane + 32]
                                           + CP[lane] * CP[lane] + CP[lane + 32] * CP[lane + 32]);
                           if (!lane) scal[7] = v; }
        __syncthreads();
    }
    const float TP = scal[5];
    const float P2 = scal[6];
    const float SRCP2 = scal[7];
    const float pBp = binv * P2 + cRC * SRCP2 + cT * TP * TP;
    const float h12v = 2.f - b128i * TP;
    const float h11v = -pBp;
    const float h22v = -4096.f * b128i;
    const float hdet = h11v * h22v - h12v * h12v;
    const float i11 = h22v / hdet, i12 = -h12v / hdet, i22 = h11v / hdet;
#pragma unroll
    for (int k = 0; k < 4; k++)
        wp[k] = binv * p[k] + cRC * (RP[aa[k]] + CP[b0]) + cT * TP;

    float TA = 0.f, TB = 0.f, D2 = 0.f, PD2 = 0.f, SA2 = 0.f, SAB = 0.f;
    float TR = 0.f, N2 = 0.f, SRC2 = 0.f, SPC = 0.f, PR = 0.f;
    float tol2 = 1e30f;
    int conv = 0, convS = 0;

    auto phaseD = [&]() {
        float sv = 0.f, sp = 0.f, sq = 0.f, spq = 0.f;
#pragma unroll
        for (int j = 0; j < 4; j++) {
            int o = rc * LD + g + 16 * j;
            float m = Dd[o], q = Pm[o];
            sv += m; sp += q * m; sq += m * m; spq += q * m * m;
        }
        sv = dual16(sv); sp = dual16(sp); sq = dual16(sq); spq = dual16(spq);
        if (!g) { RAd[rc] = sv; RBd[rc] = sp; RD2[rc] = sq; RPD2[rc] = spq; }
        float cv = 0.f, cp = 0.f;
#pragma unroll
        for (int j = 0; j < 4; j++) {
            int o = (g + 16 * j) * LD + rc;
            float m = Dd[o];
            cv += m; cp += Pm[o] * m;
        }
        cv = dual16(cv); cp = dual16(cp);
        if (!g) { CAd[rc] = cv; CBd[rc] = cp; }
        __syncthreads();
        if (w == 0)      { float v = warpSum(RAd[lane] + RAd[lane + 32]);  if (!lane) scal[0] = v; }
        else if (w == 1) { float v = warpSum(RBd[lane] + RBd[lane + 32]);  if (!lane) scal[1] = v; }
        else if (w == 2) { float v = warpSum(RD2[lane] + RD2[lane + 32]);  if (!lane) scal[2] = v; }
        else if (w == 3) { float v = warpSum(RPD2[lane] + RPD2[lane + 32]); if (!lane) scal[3] = v; }
        else if (w == 4) { float v = warpSum(RAd[lane] * RAd[lane] + RAd[lane + 32] * RAd[lane + 32]
                                           + CAd[lane] * CAd[lane] + CAd[lane + 32] * CAd[lane + 32]);
                           if (!lane) scal[4] = v; }
        else if (w == 5) { float v = warpSum(RAd[lane] * RBd[lane] + RAd[lane + 32] * RBd[lane + 32]
                                           + CAd[lane] * CBd[lane] + CAd[lane + 32] * CBd[lane + 32]);
                           if (!lane) scal[5] = v; }
        __syncthreads();
        TA = scal[0]; TB = scal[1]; D2 = scal[2]; PD2 = scal[3]; SA2 = scal[4]; SAB = scal[5];
    };

    auto phaseR = [&]() {
        float sv = 0.f, sq = 0.f, pv = 0.f;
#pragma unroll
        for (int j = 0; j < 4; j++) {
            int o = rc * LD + g + 16 * j;
            float v = Rr[o];
            sv += v; sq += v * v; pv += Pm[o] * v;
        }
        sv = dual16(sv); sq = dual16(sq); pv = dual16(pv);
        if (!g) { RAr[rc] = sv; RSQ[rc] = sq; RPR[rc] = pv; }
        float cv = 0.f;
#pragma unroll
        for (int j = 0; j < 4; j++) cv += Rr[(g + 16 * j) * LD + rc];
        cv = dual16(cv);
        if (!g) CAr[rc] = cv;
        __syncthreads();
        if (w == 0)      { float v = warpSum(RAr[lane] + RAr[lane + 32]); if (!lane) scal[0] = v; }
        else if (w == 1) { float v = warpSum(RSQ[lane] + RSQ[lane + 32]); if (!lane) scal[1] = v; }
        else if (w == 2) { float v = warpSum(RAr[lane] * RAr[lane] + RAr[lane + 32] * RAr[lane + 32]
                                           + CAr[lane] * CAr[lane] + CAr[lane + 32] * CAr[lane + 32]);
                           if (!lane) scal[2] = v; }
        else if (w == 3) { float v = warpSum(RP[lane] * RAr[lane] + RP[lane + 32] * RAr[lane + 32]
                                           + CP[lane] * CAr[lane] + CP[lane + 32] * CAr[lane + 32]);
                           if (!lane) scal[3] = v; }
        else if (w == 4) { float v = warpSum(RPR[lane] + RPR[lane + 32]); if (!lane) scal[4] = v; }
        __syncthreads();
        TR = scal[0]; N2 = scal[1]; SRC2 = scal[2]; SPC = scal[3]; PR = scal[4];
    };

    auto applyK = [&](float d, float pp, int a) -> float {
        float Ra = RAd[a], Cb = CAd[b0], Rb = RBd[a], Cv = CBd[b0];
        return beta * d + rho * (Ra + Cb)
             - 0.5f * (pp * (TA - Ra - Cb + d) + (TB - Rb - Cv + pp * d));
    };

    float s1 = 0.f, s2 = 0.f, al1 = 0.f, al2 = 0.f, rhoz = 0.f;
    auto wood = [&]() {
        s1 = binv * PR + cRC * SPC + cT * TP * TR;
        s2 = b128i * TR;
        al1 = i11 * s1 + i12 * s2;
        al2 = i12 * s1 + i22 * s2;
        rhoz = binv * N2 + cRC * SRC2 + cT * TR * TR + al1 * s1 + al2 * s2;
    };

    for (int it = 0; it < 150; ++it) {
        if ((it & 7) == 0) {
            // refresh residual from scratch: publish X, strip sums, r = rhs - Kx
#pragma unroll
            for (int k = 0; k < 4; k++) X[off[k]] = x[k];
            __syncthreads();
            {
                float sv = 0.f, sp = 0.f;
#pragma unroll
                for (int j = 0; j < 4; j++) {
                    int o = rc * LD + g + 16 * j;
                    float m = X[o];
                    sv += m; sp += Pm[o] * m;
                }
                sv = dual16(sv); sp = dual16(sp);
                if (!g) { RAd[rc] = sv; RBd[rc] = sp; }
                float cv = 0.f, cp = 0.f;
#pragma unroll
                for (int j = 0; j < 4; j++) {
                    int o = (g + 16 * j) * LD + rc;
                    float m = X[o];
                    cv += m; cp += Pm[o] * m;
                }
                cv = dual16(cv); cp = dual16(cp);
                if (!g) { CAd[rc] = cv; CBd[rc] = cp; }
            }
            __syncthreads();
            TA = warpSum(RAd[lane] + RAd[lane + 32]);
            TB = warpSum(RBd[lane] + RBd[lane + 32]);
            float loc = 0.f;
#pragma unroll
            for (int k = 0; k < 4; k++) {
                float kx = applyK(x[k], p[k], aa[k]);
                float rhs = sigma * x[k] + p[k] + (rho * z1[k] - y1[k])
                          + (rho - y2c[b0]) + (rho - y2r[aa[k]]);
                r[k] = rhs - kx;
                Rr[off[k]] = r[k];
                loc += rhs * rhs;
            }
            loc = warpSum(loc);
            if (!lane) part[w] = loc;
            __syncthreads();
            float nr = warpSum(part[lane]);
            tol2 = fmaxf(nr * 1e-7f, 1e-28f);
            if (tid < 64) { RX[tid] = RAd[tid]; CX[tid] = CAd[tid]; }
            __syncthreads();
        }

        phaseR();

        if (N2 > tol2) {
            conv = 0;
            wood();
            float rho_s = rhoz;
#pragma unroll
            for (int k = 0; k < 4; k++) {
                float z = binv * r[k] + cRC * (RAr[aa[k]] + CAr[b0]) + cT * TR
                        + al1 * wp[k] + al2 * b128i;
                dreg[k] = z;
                Dd[off[k]] = z;
            }

            float prev = 3.4e38f;
            int stag = 0;
            for (int cg = 0; cg < 60; ++cg) {
                __syncthreads();
                phaseD();
                float dq = beta * D2 + rho * SA2 - (TA * TB - SAB + PD2);
                if (!(dq > 0.f)) break;
                float alpha = rho_s / dq;
#pragma unroll
                for (int k = 0; k < 4; k++) {
                    float q = applyK(dreg[k], p[k], aa[k]);
                    x[k] += alpha * dreg[k];
                    r[k] -= alpha * q;
                    Rr[off[k]] = r[k];
                }
                if (tid < 64) {
                    RX[tid] += alpha * RAd[tid];
                    CX[tid] += alpha * CAd[tid];
                }
                __syncthreads();
                phaseR();
                if (N2 <= tol2) break;
                if (N2 >= 0.99f * prev) { if (++stag >= 3) break; }
                else stag = 0;
                prev = N2;
                wood();
                float bk = rhoz / rho_s;
                rho_s = rhoz;
#pragma unroll
                for (int k = 0; k < 4; k++) {
                    float z = binv * r[k] + cRC * (RAr[aa[k]] + CAr[b0]) + cT * TR
                            + al1 * wp[k] + al2 * b128i;
                    dreg[k] = z + bk * dreg[k];
                    Dd[off[k]] = dreg[k];
                }
            }
        } else {
            if (++conv >= 6) break;       // ADMM fixed point: x frozen, stop
        }

        // z/y updates + incremental residual; also reduce |x-xr|^2 and |x|^2
        float locD = 0.f, locX = 0.f;
#pragma unroll
        for (int k = 0; k < 4; k++) {
            float z1n = fminf(fmaxf(x[k] + y1[k] * (1.f / rho), 0.f), 1e6f);
            float dx = x[k] - xr[k];
            float rinc = sigma * dx + rho * (2.f * z1n - z1[k] - x[k])
                       - rho * (CX[b0] - 1.f) - rho * (RX[aa[k]] - 1.f);
            y1[k] += rho * (x[k] - z1n);
            z1[k] = z1n;
            r[k] += rinc;
            Rr[off[k]] = r[k];
            xr[k] = x[k];
            locD += dx * dx;
            locX += x[k] * x[k];
        }
        locD = warpSum(locD);
        locX = warpSum(locX);
        if (!lane) { part[w] = locD; prt2[w] = locX; }
        if (tid < 64) {
            y2c[tid] += rho * (CX[tid] - 1.f);
            y2r[tid] += rho * (RX[tid] - 1.f);
        }
        __syncthreads();
        float delta2 = warpSum(part[lane]);
        float x2 = warpSum(prt2[lane]);
        if (delta2 <= 4e-9f * x2 + 1e-30f) {
            if (++convS >= 2) break;      // x stagnant 2 outers: converged
        } else convS = 0;
    }

    // publish final X, then column-wise softmax: out[0][j][i] = softmax_i(200*clip)
#pragma unroll
    for (int k = 0; k < 4; k++) X[off[k]] = x[k];
    __syncthreads();
#pragma unroll
    for (int rr = 0; rr < 2; rr++) {
        int c = 2 * w + rr;
        float v1 = fminf(fmaxf(X[lane * LD + c], 0.f), 1.f);
        float v2 = fminf(fmaxf(X[(lane + 32) * LD + c], 0.f), 1.f);
        float mx = warpMax(fmaxf(v1, v2));
        float e1v = expf(200.f * (v1 - mx));
        float e2v = expf(200.f * (v2 - mx));
        float s = warpSum(e1v + e2v);
        out[c * 64 + lane] = e1v / s;
        out[c * 64 + lane + 32] = e2v / s;
    }
}

// ------------------------------------------------------------------------------------
extern "C" void kernel_launch(void* const* d_in, const int* in_sizes, int n_in,
                              void* d_out, int out_size) {
    const float* tra = (const float*)d_in[0];   // (64,512)
    const float* det = (const float*)d_in[1];   // (64,512)
    const float* iou = (const float*)d_in[2];   // (64,64)
    const float* W   = (const float*)d_in[3];   // (512,512)
    const float* b   = (const float*)d_in[4];   // (512,)
    float* out = (float*)d_out;                 // (1,64,64)

    const int SMEM_BYTES = (16640 + 16 * 64 + 64 + 8) * 4;  // 70944
    cudaFuncSetAttribute(k_admm, cudaFuncAttributeMaxDynamicSharedMemorySize, SMEM_BYTES);

    k_front1<<<128, 512>>>(tra, det, iou);
    k_egemm<<<128, 128>>>(W, b);
    k_P<<<16, 256>>>();
    k_admm<<<1, 1024, SMEM_BYTES>>>(out);
}